// round 4
// baseline (speedup 1.0000x reference)
#include <cuda_runtime.h>
#include <cuda_bf16.h>

// Problem constants
#define Bn 8
#define Tn 512
#define Dn 1024
#define Hn 16
#define DHn 64

// Scratch (allocation-free: __device__ globals). Declared as float4 so the
// base address is 16-byte aligned (float arrays only guarantee 4B).
__device__ float4 g_Q4[Bn * Hn * Tn * DHn / 4];   // [b,h,t,e]
__device__ float4 g_K4[Bn * Hn * Tn * DHn / 4];
__device__ float4 g_V4[Bn * Hn * Tn * DHn / 4];
__device__ float4 g_O4[Bn * Tn * Dn / 4];         // attention output, [b,t,h*64+e]

// ---------------------------------------------------------------------------
// Kernel 1: per-head QKV projections.
// grid = (B*H, T/64), block = 256. One block computes a 64(t) x 64(e) tile of
// Q, K and V for one (b,h), looping the 3 weight matrices through one smem buf.
// ---------------------------------------------------------------------------
__global__ __launch_bounds__(256) void qkv_kernel(
    const float* __restrict__ X,
    const float* __restrict__ Wq, const float* __restrict__ bq,
    const float* __restrict__ Wk, const float* __restrict__ bk,
    const float* __restrict__ Wv, const float* __restrict__ bv)
{
    const int bh = blockIdx.x;
    const int b = bh >> 4;
    const int h = bh & 15;
    const int t0 = blockIdx.y * 64;
    const int tid = threadIdx.x;

    // Row stride 68 floats = 272 bytes = multiple of 16 -> float4-aligned rows,
    // while still skewing banks (68 mod 32 != 0).
    __shared__ float XsT[64][68];   // [d][r]
    __shared__ float Ws[64][64];    // [d][e]

    // Load X tile (rows t0..t0+63, cols h*64..h*64+63), transposed into smem.
#pragma unroll
    for (int i = 0; i < 4; i++) {
        int idx = tid + i * 256;          // float4 index 0..1023
        int r = idx >> 4;
        int d4 = (idx & 15) << 2;
        float4 xv = *(const float4*)(X + (size_t)(b * Tn + t0 + r) * Dn + h * DHn + d4);
        XsT[d4 + 0][r] = xv.x;
        XsT[d4 + 1][r] = xv.y;
        XsT[d4 + 2][r] = xv.z;
        XsT[d4 + 3][r] = xv.w;
    }

    const int tx = tid & 15, ty = tid >> 4;
    const int r0 = ty * 4, c0 = tx * 4;

    const float* Wsrc[3] = { Wq + h * DHn * DHn, Wk + h * DHn * DHn, Wv + h * DHn * DHn };
    const float* bsrc[3] = { bq + h * DHn, bk + h * DHn, bv + h * DHn };
    float* dsts[3] = { (float*)g_Q4, (float*)g_K4, (float*)g_V4 };

    for (int w = 0; w < 3; w++) {
        __syncthreads();  // previous phase done reading Ws
#pragma unroll
        for (int i = 0; i < 4; i++) {
            int idx = tid + i * 256;
            int d = idx >> 4;
            int e4 = (idx & 15) << 2;
            *(float4*)&Ws[d][e4] = *(const float4*)(Wsrc[w] + d * DHn + e4);
        }
        __syncthreads();

        float acc[4][4];
        float4 bv4 = *(const float4*)(bsrc[w] + c0);
#pragma unroll
        for (int i = 0; i < 4; i++) {
            acc[i][0] = bv4.x; acc[i][1] = bv4.y; acc[i][2] = bv4.z; acc[i][3] = bv4.w;
        }

#pragma unroll 8
        for (int d = 0; d < 64; d++) {
            float4 xr = *(float4*)&XsT[d][r0];
            float4 wr = *(float4*)&Ws[d][c0];
            float xa[4] = { xr.x, xr.y, xr.z, xr.w };
            float wa[4] = { wr.x, wr.y, wr.z, wr.w };
#pragma unroll
            for (int i = 0; i < 4; i++)
#pragma unroll
                for (int j = 0; j < 4; j++)
                    acc[i][j] += xa[i] * wa[j];
        }

        float* dst = dsts[w] + ((size_t)bh * Tn + t0 + r0) * DHn + c0;
#pragma unroll
        for (int i = 0; i < 4; i++) {
            float4 o = make_float4(acc[i][0], acc[i][1], acc[i][2], acc[i][3]);
            *(float4*)(dst + (size_t)i * DHn) = o;
        }
    }
}

// ---------------------------------------------------------------------------
// Kernel 2: flash attention. grid = (B*H, T/128), block = 128.
// One thread owns one query row: q[64] and acc[64] in registers; K/V tiles of
// 64 keys in smem (all reads broadcast). Online softmax in chunks of 32 keys.
// Output written directly in concatenated [B,T,D] layout.
// ---------------------------------------------------------------------------
__global__ __launch_bounds__(128) void attn_kernel(const int* __restrict__ mask)
{
    const int bh = blockIdx.x;
    const int b = bh >> 4;
    const int tid = threadIdx.x;
    const int h = bh & 15;
    const int qi = blockIdx.y * 128 + tid;

    __shared__ float Ks[64][64];
    __shared__ float Vs[64][64];
    __shared__ float mbad[64];   // 1.0 => masked out

    float q[64];
    {
        const float* Qp = (const float*)g_Q4 + ((size_t)bh * Tn + qi) * DHn;
#pragma unroll
        for (int i = 0; i < 16; i++) {
            float4 v = *(const float4*)(Qp + i * 4);
            q[i * 4 + 0] = v.x * 0.125f;   // 1/sqrt(64)
            q[i * 4 + 1] = v.y * 0.125f;
            q[i * 4 + 2] = v.z * 0.125f;
            q[i * 4 + 3] = v.w * 0.125f;
        }
    }

    float acc[64];
#pragma unroll
    for (int e = 0; e < 64; e++) acc[e] = 0.f;
    float m = -3.4e38f, l = 0.f;

    for (int kt = 0; kt < 8; kt++) {
        __syncthreads();
        const float* Kp = (const float*)g_K4 + ((size_t)bh * Tn + kt * 64) * DHn;
        const float* Vp = (const float*)g_V4 + ((size_t)bh * Tn + kt * 64) * DHn;
#pragma unroll
        for (int i = 0; i < 8; i++) {
            int idx = tid + i * 128;       // float4 index 0..1023
            int j = idx >> 4;
            int d4 = (idx & 15) << 2;
            *(float4*)&Ks[j][d4] = *(const float4*)(Kp + j * DHn + d4);
            *(float4*)&Vs[j][d4] = *(const float4*)(Vp + j * DHn + d4);
        }
        if (tid < 64) mbad[tid] = (mask[b * Tn + kt * 64 + tid] > 0) ? 0.f : 1.f;
        __syncthreads();

#pragma unroll
        for (int ch = 0; ch < 2; ch++) {
            float s[32];
            float cmax = -3.4e38f;
#pragma unroll
            for (int jj = 0; jj < 32; jj++) {
                int j = ch * 32 + jj;
                float v0 = 0.f, v1 = 0.f, v2 = 0.f, v3 = 0.f;
#pragma unroll
                for (int d4 = 0; d4 < 16; d4++) {
                    float4 kv = *(float4*)&Ks[j][d4 * 4];
                    v0 += q[d4 * 4 + 0] * kv.x;
                    v1 += q[d4 * 4 + 1] * kv.y;
                    v2 += q[d4 * 4 + 2] * kv.z;
                    v3 += q[d4 * 4 + 3] * kv.w;
                }
                float v = (v0 + v1) + (v2 + v3);
                v = (mbad[j] != 0.f) ? -1e9f : v;
                s[jj] = v;
                cmax = fmaxf(cmax, v);
            }
            float mnew = fmaxf(m, cmax);
            float corr = __expf(m - mnew);
            l *= corr;
#pragma unroll
            for (int e = 0; e < 64; e++) acc[e] *= corr;
#pragma unroll
            for (int jj = 0; jj < 32; jj++) {
                int j = ch * 32 + jj;
                float p = __expf(s[jj] - mnew);
                l += p;
#pragma unroll
                for (int e4 = 0; e4 < 16; e4++) {
                    float4 vv = *(float4*)&Vs[j][e4 * 4];
                    acc[e4 * 4 + 0] += p * vv.x;
                    acc[e4 * 4 + 1] += p * vv.y;
                    acc[e4 * 4 + 2] += p * vv.z;
                    acc[e4 * 4 + 3] += p * vv.w;
                }
            }
            m = mnew;
        }
    }

    const float inv = 1.f / l;
    float* Op = (float*)g_O4 + ((size_t)(b * Tn + qi)) * Dn + h * DHn;
#pragma unroll
    for (int e4 = 0; e4 < 16; e4++) {
        float4 o = make_float4(acc[e4 * 4 + 0] * inv, acc[e4 * 4 + 1] * inv,
                               acc[e4 * 4 + 2] * inv, acc[e4 * 4 + 3] * inv);
        *(float4*)(Op + e4 * 4) = o;
    }
}

// ---------------------------------------------------------------------------
// Kernel 3: fusion GEMM  out[4096,1024] = g_O @ Wf + bf.
// 128x128 block tile, BK=16, 256 threads, 8x8 micro-tiles, double-buffered.
// ---------------------------------------------------------------------------
__global__ __launch_bounds__(256) void fuse_kernel(
    const float* __restrict__ Wf, const float* __restrict__ bf,
    float* __restrict__ out)
{
    const int Kd = 1024, Nd = 1024;
    const int bn = blockIdx.x * 128;
    const int bm = blockIdx.y * 128;
    const int tid = threadIdx.x;

    __shared__ float As[2][16][128];   // [k][m]
    __shared__ float Bs[2][16][128];   // [k][n]

    const float* A = (const float*)g_O4;

    const int tx = tid & 15, ty = tid >> 4;
    const int m0 = ty * 8, n0 = tx * 8;

    float acc[8][8];
    {
        float4 b0 = *(const float4*)(bf + bn + n0);
        float4 b1 = *(const float4*)(bf + bn + n0 + 4);
#pragma unroll
        for (int i = 0; i < 8; i++) {
            acc[i][0] = b0.x; acc[i][1] = b0.y; acc[i][2] = b0.z; acc[i][3] = b0.w;
            acc[i][4] = b1.x; acc[i][5] = b1.y; acc[i][6] = b1.z; acc[i][7] = b1.w;
        }
    }

    // A-load mapping: 512 float4 -> m = idx>>2, k4 = (idx&3)*4
    const int a_m = tid >> 2;            // first of two rows handled (i*64 apart)
    const int a_k4 = (tid & 3) << 2;
    // B-load mapping: 512 float4 -> k = idx>>5, n4 = (idx&31)*4
    const int b_k = tid >> 5;            // first of two k rows (i*8 apart)
    const int b_n4 = (tid & 31) << 2;

    // Preload tile 0 directly to smem buffer 0
    {
#pragma unroll
        for (int i = 0; i < 2; i++) {
            int m = a_m + i * 64;
            float4 av = *(const float4*)(A + (size_t)(bm + m) * Kd + a_k4);
            As[0][a_k4 + 0][m] = av.x;
            As[0][a_k4 + 1][m] = av.y;
            As[0][a_k4 + 2][m] = av.z;
            As[0][a_k4 + 3][m] = av.w;
            int k = b_k + i * 8;
            *(float4*)&Bs[0][k][b_n4] = *(const float4*)(Wf + (size_t)k * Nd + bn + b_n4);
        }
    }
    __syncthreads();

    for (int k0 = 0; k0 < Kd; k0 += 16) {
        const int buf = (k0 >> 4) & 1;
        float4 pa[2], pb[2];
        const bool has_next = (k0 + 16) < Kd;
        if (has_next) {
#pragma unroll
            for (int i = 0; i < 2; i++) {
                int m = a_m + i * 64;
                pa[i] = *(const float4*)(A + (size_t)(bm + m) * Kd + k0 + 16 + a_k4);
                int k = b_k + i * 8;
                pb[i] = *(const float4*)(Wf + (size_t)(k0 + 16 + k) * Nd + bn + b_n4);
            }
        }

#pragma unroll
        for (int k = 0; k < 16; k++) {
            float a[8], bb[8];
            *(float4*)&a[0] = *(float4*)&As[buf][k][m0];
            *(float4*)&a[4] = *(float4*)&As[buf][k][m0 + 4];
            *(float4*)&bb[0] = *(float4*)&Bs[buf][k][n0];
            *(float4*)&bb[4] = *(float4*)&Bs[buf][k][n0 + 4];
#pragma unroll
            for (int i = 0; i < 8; i++)
#pragma unroll
                for (int j = 0; j < 8; j++)
                    acc[i][j] += a[i] * bb[j];
        }

        if (has_next) {
            const int nb = buf ^ 1;
#pragma unroll
            for (int i = 0; i < 2; i++) {
                int m = a_m + i * 64;
                As[nb][a_k4 + 0][m] = pa[i].x;
                As[nb][a_k4 + 1][m] = pa[i].y;
                As[nb][a_k4 + 2][m] = pa[i].z;
                As[nb][a_k4 + 3][m] = pa[i].w;
                int k = b_k + i * 8;
                *(float4*)&Bs[nb][k][b_n4] = pb[i];
            }
        }
        __syncthreads();
    }

#pragma unroll
    for (int i = 0; i < 8; i++) {
        float4 o0 = make_float4(acc[i][0], acc[i][1], acc[i][2], acc[i][3]);
        float4 o1 = make_float4(acc[i][4], acc[i][5], acc[i][6], acc[i][7]);
        float* p = out + (size_t)(bm + m0 + i) * Nd + bn + n0;
        *(float4*)(p) = o0;
        *(float4*)(p + 4) = o1;
    }
}

// ---------------------------------------------------------------------------
extern "C" void kernel_launch(void* const* d_in, const int* in_sizes, int n_in,
                              void* d_out, int out_size)
{
    const float* X    = (const float*)d_in[0];
    const int*   mask = (const int*)  d_in[1];
    const float* Wq   = (const float*)d_in[2];
    const float* bq   = (const float*)d_in[3];
    const float* Wk   = (const float*)d_in[4];
    const float* bk   = (const float*)d_in[5];
    const float* Wv   = (const float*)d_in[6];
    const float* bv   = (const float*)d_in[7];
    const float* Wf   = (const float*)d_in[8];
    const float* bf   = (const float*)d_in[9];
    float* out = (float*)d_out;

    qkv_kernel<<<dim3(Bn * Hn, Tn / 64), 256>>>(X, Wq, bq, Wk, bk, Wv, bv);
    attn_kernel<<<dim3(Bn * Hn, Tn / 128), 128>>>(mask);
    fuse_kernel<<<dim3(Dn / 128, (Bn * Tn) / 128), 256>>>(Wf, bf, out);
}

// round 6
// speedup vs baseline: 1.2945x; 1.2945x over previous
#include <cuda_runtime.h>
#include <cuda_bf16.h>
#include <cstdint>

// Problem constants
#define Bn 8
#define Tn 512
#define Dn 1024
#define Hn 16
#define DHn 64
#define FK 3072   // virtual K = 3*1024 for split-bf16 fusion GEMM

// Scratch (allocation-free __device__ globals; uint4/float4 for 16B alignment)
__device__ float4 g_Q4[Bn * Hn * Tn * DHn / 4];
__device__ float4 g_K4[Bn * Hn * Tn * DHn / 4];
__device__ float4 g_V4[Bn * Hn * Tn * DHn / 4];
__device__ uint4  g_A4[(size_t)Bn * Tn * FK * 2 / 16];  // bf16 A' [4096][3072]: [hi|hi|lo]
__device__ uint4  g_B4[(size_t)Dn * FK * 2 / 16];       // bf16 B' [1024][3072]: [hi|lo|hi] (Wf^T)

__device__ __forceinline__ uint32_t smem_u32(const void* p) {
    uint32_t a;
    asm("{ .reg .u64 t; cvta.to.shared.u64 t, %1; cvt.u32.u64 %0, t; }" : "=r"(a) : "l"(p));
    return a;
}

// ---------------------------------------------------------------------------
// Kernel 1: per-head QKV projections (unchanged, measured 47us).
// ---------------------------------------------------------------------------
__global__ __launch_bounds__(256) void qkv_kernel(
    const float* __restrict__ X,
    const float* __restrict__ Wq, const float* __restrict__ bq,
    const float* __restrict__ Wk, const float* __restrict__ bk,
    const float* __restrict__ Wv, const float* __restrict__ bv)
{
    const int bh = blockIdx.x;
    const int b = bh >> 4;
    const int h = bh & 15;
    const int t0 = blockIdx.y * 64;
    const int tid = threadIdx.x;

    __shared__ float XsT[64][68];   // row stride 272B: float4-aligned + bank-skewed
    __shared__ float Ws[64][64];

#pragma unroll
    for (int i = 0; i < 4; i++) {
        int idx = tid + i * 256;
        int r = idx >> 4;
        int d4 = (idx & 15) << 2;
        float4 xv = *(const float4*)(X + (size_t)(b * Tn + t0 + r) * Dn + h * DHn + d4);
        XsT[d4 + 0][r] = xv.x; XsT[d4 + 1][r] = xv.y;
        XsT[d4 + 2][r] = xv.z; XsT[d4 + 3][r] = xv.w;
    }

    const int tx = tid & 15, ty = tid >> 4;
    const int r0 = ty * 4, c0 = tx * 4;

    const float* Wsrc[3] = { Wq + h * DHn * DHn, Wk + h * DHn * DHn, Wv + h * DHn * DHn };
    const float* bsrc[3] = { bq + h * DHn, bk + h * DHn, bv + h * DHn };
    float* dsts[3] = { (float*)g_Q4, (float*)g_K4, (float*)g_V4 };

    for (int w = 0; w < 3; w++) {
        __syncthreads();
#pragma unroll
        for (int i = 0; i < 4; i++) {
            int idx = tid + i * 256;
            int d = idx >> 4;
            int e4 = (idx & 15) << 2;
            *(float4*)&Ws[d][e4] = *(const float4*)(Wsrc[w] + d * DHn + e4);
        }
        __syncthreads();

        float acc[4][4];
        float4 bv4 = *(const float4*)(bsrc[w] + c0);
#pragma unroll
        for (int i = 0; i < 4; i++) {
            acc[i][0] = bv4.x; acc[i][1] = bv4.y; acc[i][2] = bv4.z; acc[i][3] = bv4.w;
        }
#pragma unroll 8
        for (int d = 0; d < 64; d++) {
            float4 xr = *(float4*)&XsT[d][r0];
            float4 wr = *(float4*)&Ws[d][c0];
            float xa[4] = { xr.x, xr.y, xr.z, xr.w };
            float wa[4] = { wr.x, wr.y, wr.z, wr.w };
#pragma unroll
            for (int i = 0; i < 4; i++)
#pragma unroll
                for (int j = 0; j < 4; j++)
                    acc[i][j] += xa[i] * wa[j];
        }
        float* dst = dsts[w] + ((size_t)bh * Tn + t0 + r0) * DHn + c0;
#pragma unroll
        for (int i = 0; i < 4; i++)
            *(float4*)(dst + (size_t)i * DHn) = make_float4(acc[i][0], acc[i][1], acc[i][2], acc[i][3]);
    }
}

// ---------------------------------------------------------------------------
// Kernel 2: flash attention, 2 threads per query (d/e split + shfl-combine).
// grid = (B*H, T/64), block = 128 (64 queries). Emits split-bf16 A' rows:
// cols [0,1024)=hi, [1024,2048)=hi, [2048,3072)=lo.
// ---------------------------------------------------------------------------
__global__ __launch_bounds__(128) void attn_kernel(const int* __restrict__ mask)
{
    const int bh = blockIdx.x;
    const int b = bh >> 4;
    const int h = bh & 15;
    const int tid = threadIdx.x;
    const int qlocal = tid >> 1;
    const int p = tid & 1;
    const int p32 = p * 32;
    const int qi = blockIdx.y * 64 + qlocal;

    __shared__ float Ks[64][64];
    __shared__ float Vs[64][64];
    __shared__ float mbad[64];

    float q[32];
    {
        const float* Qp = (const float*)g_Q4 + ((size_t)bh * Tn + qi) * DHn + p32;
#pragma unroll
        for (int i = 0; i < 8; i++) {
            float4 v = *(const float4*)(Qp + i * 4);
            q[i * 4 + 0] = v.x * 0.125f;
            q[i * 4 + 1] = v.y * 0.125f;
            q[i * 4 + 2] = v.z * 0.125f;
            q[i * 4 + 3] = v.w * 0.125f;
        }
    }

    float acc[32];
#pragma unroll
    for (int e = 0; e < 32; e++) acc[e] = 0.f;
    float m = -3.4e38f, l = 0.f;

    for (int kt = 0; kt < 8; kt++) {
        __syncthreads();
        const float* Kp = (const float*)g_K4 + ((size_t)bh * Tn + kt * 64) * DHn;
        const float* Vp = (const float*)g_V4 + ((size_t)bh * Tn + kt * 64) * DHn;
#pragma unroll
        for (int i = 0; i < 8; i++) {
            int idx = tid + i * 128;
            int j = idx >> 4;
            int d4 = (idx & 15) << 2;
            *(float4*)&Ks[j][d4] = *(const float4*)(Kp + j * DHn + d4);
            *(float4*)&Vs[j][d4] = *(const float4*)(Vp + j * DHn + d4);
        }
        if (tid < 64) mbad[tid] = (mask[b * Tn + kt * 64 + tid] > 0) ? 0.f : 1.f;
        __syncthreads();

#pragma unroll
        for (int ch = 0; ch < 4; ch++) {
            float s[16];
            float cmax = -3.4e38f;
#pragma unroll
            for (int jj = 0; jj < 16; jj++) {
                int j = ch * 16 + jj;
                float v0 = 0.f, v1 = 0.f, v2 = 0.f, v3 = 0.f;
#pragma unroll
                for (int d4 = 0; d4 < 8; d4++) {
                    float4 kv = *(float4*)&Ks[j][p32 + d4 * 4];
                    v0 += q[d4 * 4 + 0] * kv.x;
                    v1 += q[d4 * 4 + 1] * kv.y;
                    v2 += q[d4 * 4 + 2] * kv.z;
                    v3 += q[d4 * 4 + 3] * kv.w;
                }
                float part = (v0 + v1) + (v2 + v3);
                float tot = part + __shfl_xor_sync(0xffffffffu, part, 1);
                tot = (mbad[j] != 0.f) ? -1e9f : tot;
                s[jj] = tot;
                cmax = fmaxf(cmax, tot);
            }
            float mnew = fmaxf(m, cmax);
            float corr = __expf(m - mnew);
            l *= corr;
#pragma unroll
            for (int e = 0; e < 32; e++) acc[e] *= corr;
#pragma unroll
            for (int jj = 0; jj < 16; jj++) {
                int j = ch * 16 + jj;
                float pw = __expf(s[jj] - mnew);
                l += pw;
#pragma unroll
                for (int e4 = 0; e4 < 8; e4++) {
                    float4 vv = *(float4*)&Vs[j][p32 + e4 * 4];
                    acc[e4 * 4 + 0] += pw * vv.x;
                    acc[e4 * 4 + 1] += pw * vv.y;
                    acc[e4 * 4 + 2] += pw * vv.z;
                    acc[e4 * 4 + 3] += pw * vv.w;
                }
            }
            m = mnew;
        }
    }

    const float inv = 1.f / l;
    const int row = b * Tn + qi;
    __nv_bfloat16* Ap = (__nv_bfloat16*)g_A4 + (size_t)row * FK + h * DHn + p32;
#pragma unroll
    for (int e2 = 0; e2 < 16; e2++) {
        float o0 = acc[e2 * 2 + 0] * inv;
        float o1 = acc[e2 * 2 + 1] * inv;
        __nv_bfloat16 h0 = __float2bfloat16(o0);
        __nv_bfloat16 h1 = __float2bfloat16(o1);
        __nv_bfloat162 hp; hp.x = h0; hp.y = h1;
        __nv_bfloat162 lp;
        lp.x = __float2bfloat16(o0 - __bfloat162float(h0));
        lp.y = __float2bfloat16(o1 - __bfloat162float(h1));
        *(__nv_bfloat162*)(Ap + e2 * 2)        = hp;   // pass 0: hi (x B hi)
        *(__nv_bfloat162*)(Ap + 1024 + e2 * 2) = hp;   // pass 1: hi (x B lo)
        *(__nv_bfloat162*)(Ap + 2048 + e2 * 2) = lp;   // pass 2: lo (x B hi)
    }
}

// ---------------------------------------------------------------------------
// Kernel 3: build B' = split-bf16 transpose of Wf.
// B'[n][k'] : k' in [0,1024)=hi(Wf[k][n]), [1024,2048)=lo, [2048,3072)=hi.
// ---------------------------------------------------------------------------
__global__ __launch_bounds__(256) void convw_kernel(const float* __restrict__ Wf)
{
    __shared__ float t[32][33];
    const int tx = threadIdx.x & 31, ty = threadIdx.x >> 5;
    const int n0 = blockIdx.x * 32, k0 = blockIdx.y * 32;

#pragma unroll
    for (int r = 0; r < 4; r++)
        t[ty + r * 8][tx] = Wf[(size_t)(k0 + ty + r * 8) * Dn + n0 + tx];
    __syncthreads();

    __nv_bfloat16* Bg = (__nv_bfloat16*)g_B4;
#pragma unroll
    for (int r = 0; r < 4; r++) {
        int n = n0 + ty + r * 8;
        int k = k0 + tx;
        float w = t[tx][ty + r * 8];
        __nv_bfloat16 hi = __float2bfloat16(w);
        __nv_bfloat16 lo = __float2bfloat16(w - __bfloat162float(hi));
        size_t base = (size_t)n * FK + k;
        Bg[base]        = hi;   // pass 0
        Bg[base + 1024] = lo;   // pass 1
        Bg[base + 2048] = hi;   // pass 2
    }
}

// ---------------------------------------------------------------------------
// Kernel 4: fusion GEMM via mma.sync (HMMA, base ISA — tcgen05 unavailable on
// this toolchain's sm_103 target). out[4096,1024] = A'·B'^T + bf over virtual
// K=3072. Block 128x128, 8 warps (32m x 64n each), BK=32, double-buffered smem
// with 40-bf16 (80B) padded rows -> conflict-free ldmatrix.
// ---------------------------------------------------------------------------
#define FNCH (FK / 32)   // 96 chunks

__global__ __launch_bounds__(256) void fuse_mma_kernel(
    const float* __restrict__ bfv, float* __restrict__ out)
{
    __shared__ __nv_bfloat16 As[2][128][40];
    __shared__ __nv_bfloat16 Bs[2][128][40];

    const int tid = threadIdx.x;
    const int wid = tid >> 5;
    const int lane = tid & 31;
    const int bm = blockIdx.y * 128;
    const int bn = blockIdx.x * 128;
    const int wm = (wid >> 1) * 32;   // warp m offset (4 warps in m)
    const int wn = (wid & 1) * 64;    // warp n offset (2 warps in n)

    const __nv_bfloat16* Ag = (const __nv_bfloat16*)g_A4;
    const __nv_bfloat16* Bg = (const __nv_bfloat16*)g_B4;

    float acc[2][8][4];
#pragma unroll
    for (int mt = 0; mt < 2; mt++)
#pragma unroll
        for (int nt = 0; nt < 8; nt++)
#pragma unroll
            for (int r = 0; r < 4; r++) acc[mt][nt][r] = 0.f;

    const int l_row = tid >> 2;          // 0..63 (first of 2 rows, +64 apart)
    const int l_c16 = tid & 3;           // 16B column within 32-col chunk

    // prologue: chunk 0 -> buffer 0
    {
#pragma unroll
        for (int i = 0; i < 2; i++) {
            int row = l_row + i * 64;
            *(uint4*)&As[0][row][l_c16 * 8] = *(const uint4*)(Ag + (size_t)(bm + row) * FK + l_c16 * 8);
            *(uint4*)&Bs[0][row][l_c16 * 8] = *(const uint4*)(Bg + (size_t)(bn + row) * FK + l_c16 * 8);
        }
    }
    __syncthreads();

    for (int c = 0; c < FNCH; c++) {
        const int buf = c & 1;
        uint4 pa[2], pb[2];
        if (c + 1 < FNCH) {
#pragma unroll
            for (int i = 0; i < 2; i++) {
                int row = l_row + i * 64;
                pa[i] = *(const uint4*)(Ag + (size_t)(bm + row) * FK + (c + 1) * 32 + l_c16 * 8);
                pb[i] = *(const uint4*)(Bg + (size_t)(bn + row) * FK + (c + 1) * 32 + l_c16 * 8);
            }
        }

#pragma unroll
        for (int ks = 0; ks < 2; ks++) {
            const int k0 = ks * 16;
            uint32_t af[2][4];
#pragma unroll
            for (int mt = 0; mt < 2; mt++) {
                uint32_t addr = smem_u32(&As[buf][wm + mt * 16 + (lane & 15)][k0 + (lane >> 4) * 8]);
                asm volatile("ldmatrix.sync.aligned.m8n8.x4.shared.b16 {%0,%1,%2,%3}, [%4];"
                             : "=r"(af[mt][0]), "=r"(af[mt][1]), "=r"(af[mt][2]), "=r"(af[mt][3])
                             : "r"(addr));
            }
            uint32_t bfr[8][2];
#pragma unroll
            for (int nt = 0; nt < 8; nt++) {
                uint32_t addr = smem_u32(&Bs[buf][wn + nt * 8 + (lane & 7)][k0 + ((lane >> 3) & 1) * 8]);
                asm volatile("ldmatrix.sync.aligned.m8n8.x2.shared.b16 {%0,%1}, [%2];"
                             : "=r"(bfr[nt][0]), "=r"(bfr[nt][1]) : "r"(addr));
            }
#pragma unroll
            for (int mt = 0; mt < 2; mt++)
#pragma unroll
                for (int nt = 0; nt < 8; nt++)
                    asm volatile(
                        "mma.sync.aligned.m16n8k16.row.col.f32.bf16.bf16.f32 "
                        "{%0,%1,%2,%3}, {%4,%5,%6,%7}, {%8,%9}, {%0,%1,%2,%3};"
                        : "+f"(acc[mt][nt][0]), "+f"(acc[mt][nt][1]),
                          "+f"(acc[mt][nt][2]), "+f"(acc[mt][nt][3])
                        : "r"(af[mt][0]), "r"(af[mt][1]), "r"(af[mt][2]), "r"(af[mt][3]),
                          "r"(bfr[nt][0]), "r"(bfr[nt][1]));
        }

        if (c + 1 < FNCH) {
            const int nb = buf ^ 1;
#pragma unroll
            for (int i = 0; i < 2; i++) {
                int row = l_row + i * 64;
                *(uint4*)&As[nb][row][l_c16 * 8] = pa[i];
                *(uint4*)&Bs[nb][row][l_c16 * 8] = pb[i];
            }
        }
        __syncthreads();
    }

    // epilogue: C fragment layout m16n8: c0,c1 row=lane>>2 col=(lane&3)*2; c2,c3 row+8
#pragma unroll
    for (int mt = 0; mt < 2; mt++) {
        const int row0 = bm + wm + mt * 16 + (lane >> 2);
#pragma unroll
        for (int nt = 0; nt < 8; nt++) {
            const int col = bn + wn + nt * 8 + (lane & 3) * 2;
            const float b0 = bfv[col], b1 = bfv[col + 1];
            float* p0 = out + (size_t)row0 * Dn + col;
            float* p1 = out + (size_t)(row0 + 8) * Dn + col;
            p0[0] = acc[mt][nt][0] + b0;
            p0[1] = acc[mt][nt][1] + b1;
            p1[0] = acc[mt][nt][2] + b0;
            p1[1] = acc[mt][nt][3] + b1;
        }
    }
}

// ---------------------------------------------------------------------------
extern "C" void kernel_launch(void* const* d_in, const int* in_sizes, int n_in,
                              void* d_out, int out_size)
{
    const float* X    = (const float*)d_in[0];
    const int*   mask = (const int*)  d_in[1];
    const float* Wq   = (const float*)d_in[2];
    const float* bq   = (const float*)d_in[3];
    const float* Wk   = (const float*)d_in[4];
    const float* bk   = (const float*)d_in[5];
    const float* Wv   = (const float*)d_in[6];
    const float* bv   = (const float*)d_in[7];
    const float* Wf   = (const float*)d_in[8];
    const float* bfp  = (const float*)d_in[9];
    float* out = (float*)d_out;

    qkv_kernel<<<dim3(Bn * Hn, Tn / 64), 256>>>(X, Wq, bq, Wk, bk, Wv, bv);
    attn_kernel<<<dim3(Bn * Hn, Tn / 64), 128>>>(mask);
    convw_kernel<<<dim3(Dn / 32, Dn / 32), 256>>>(Wf);
    fuse_mma_kernel<<<dim3(Dn / 128, (Bn * Tn) / 128), 256>>>(bfp, out);
}

// round 11
// speedup vs baseline: 3.0688x; 2.3706x over previous
#include <cuda_runtime.h>
#include <cuda_bf16.h>
#include <cstdint>

// Problem constants
#define Bn 8
#define Tn 512
#define Dn 1024
#define Hn 16
#define DHn 64
#define FK 3072   // virtual K = 3*1024 for split-bf16 fusion GEMM

// Scratch (allocation-free __device__ globals; uint4 => 16B alignment)
__device__ uint4 g_A4[(size_t)Bn * Tn * FK * 2 / 16];  // bf16 A' [4096][3072]: [hi|hi|lo]
__device__ uint4 g_B4[(size_t)Dn * FK * 2 / 16];       // bf16 B' [1024][3072]: [hi|lo|hi] (Wf^T)
// Attention operands (bf16), per (b,h):
__device__ uint4 g_Qh4[Bn * Hn * Tn * DHn * 2 / 16];   // [bh][t][64] hi, pre-scaled 1/8
__device__ uint4 g_Ql4[Bn * Hn * Tn * DHn * 2 / 16];   // lo
__device__ uint4 g_Kh4[Bn * Hn * Tn * DHn * 2 / 16];   // [bh][t][64]
__device__ uint4 g_Kl4[Bn * Hn * Tn * DHn * 2 / 16];
__device__ uint4 g_Vh4[Bn * Hn * Tn * DHn * 2 / 16];   // [bh][d][t]  (transposed)
__device__ uint4 g_Vl4[Bn * Hn * Tn * DHn * 2 / 16];

__device__ __forceinline__ uint32_t smem_u32(const void* p) {
    uint32_t a;
    asm("{ .reg .u64 t; cvta.to.shared.u64 t, %1; cvt.u32.u64 %0, t; }" : "=r"(a) : "l"(p));
    return a;
}
__device__ __forceinline__ uint32_t pack_bf16(float a, float b) {
    __nv_bfloat162 t = __floats2bfloat162_rn(a, b);
    return *(uint32_t*)&t;
}
__device__ __forceinline__ void mma_bf16(float* c, const uint32_t* a, const uint32_t* b) {
    asm volatile(
        "mma.sync.aligned.m16n8k16.row.col.f32.bf16.bf16.f32 "
        "{%0,%1,%2,%3}, {%4,%5,%6,%7}, {%8,%9}, {%0,%1,%2,%3};"
        : "+f"(c[0]), "+f"(c[1]), "+f"(c[2]), "+f"(c[3])
        : "r"(a[0]), "r"(a[1]), "r"(a[2]), "r"(a[3]), "r"(b[0]), "r"(b[1]));
}

// ---------------------------------------------------------------------------
// Kernel 1: per-head QKV projections -> split-bf16 operands.
// grid = (B*H, T/64), block = 256.
// ---------------------------------------------------------------------------
__global__ __launch_bounds__(256) void qkv_kernel(
    const float* __restrict__ X,
    const float* __restrict__ Wq, const float* __restrict__ bq,
    const float* __restrict__ Wk, const float* __restrict__ bk,
    const float* __restrict__ Wv, const float* __restrict__ bv)
{
    const int bh = blockIdx.x;
    const int b = bh >> 4;
    const int h = bh & 15;
    const int t0 = blockIdx.y * 64;
    const int tid = threadIdx.x;

    __shared__ float XsT[64][68];
    __shared__ float Ws[64][64];

#pragma unroll
    for (int i = 0; i < 4; i++) {
        int idx = tid + i * 256;
        int r = idx >> 4;
        int d4 = (idx & 15) << 2;
        float4 xv = *(const float4*)(X + (size_t)(b * Tn + t0 + r) * Dn + h * DHn + d4);
        XsT[d4 + 0][r] = xv.x; XsT[d4 + 1][r] = xv.y;
        XsT[d4 + 2][r] = xv.z; XsT[d4 + 3][r] = xv.w;
    }

    const int tx = tid & 15, ty = tid >> 4;
    const int r0 = ty * 4, c0 = tx * 4;

    const float* Wsrc[3] = { Wq + h * DHn * DHn, Wk + h * DHn * DHn, Wv + h * DHn * DHn };
    const float* bsrc[3] = { bq + h * DHn, bk + h * DHn, bv + h * DHn };

    for (int w = 0; w < 3; w++) {
        __syncthreads();
#pragma unroll
        for (int i = 0; i < 4; i++) {
            int idx = tid + i * 256;
            int d = idx >> 4;
            int e4 = (idx & 15) << 2;
            *(float4*)&Ws[d][e4] = *(const float4*)(Wsrc[w] + d * DHn + e4);
        }
        __syncthreads();

        float acc[4][4];
        float4 bv4 = *(const float4*)(bsrc[w] + c0);
#pragma unroll
        for (int i = 0; i < 4; i++) {
            acc[i][0] = bv4.x; acc[i][1] = bv4.y; acc[i][2] = bv4.z; acc[i][3] = bv4.w;
        }
#pragma unroll 8
        for (int d = 0; d < 64; d++) {
            float4 xr = *(float4*)&XsT[d][r0];
            float4 wr = *(float4*)&Ws[d][c0];
            float xa[4] = { xr.x, xr.y, xr.z, xr.w };
            float wa[4] = { wr.x, wr.y, wr.z, wr.w };
#pragma unroll
            for (int i = 0; i < 4; i++)
#pragma unroll
                for (int j = 0; j < 4; j++)
                    acc[i][j] += xa[i] * wa[j];
        }

        const float scale = (w == 0) ? 0.125f : 1.0f;
        if (w < 2) {
            __nv_bfloat16* dh = (__nv_bfloat16*)(w == 0 ? g_Qh4 : g_Kh4)
                                + ((size_t)bh * Tn + t0 + r0) * DHn + c0;
            __nv_bfloat16* dl = (__nv_bfloat16*)(w == 0 ? g_Ql4 : g_Kl4)
                                + ((size_t)bh * Tn + t0 + r0) * DHn + c0;
#pragma unroll
            for (int i = 0; i < 4; i++) {
#pragma unroll
                for (int j2 = 0; j2 < 2; j2++) {
                    float v0 = acc[i][j2 * 2 + 0] * scale;
                    float v1 = acc[i][j2 * 2 + 1] * scale;
                    __nv_bfloat16 h0 = __float2bfloat16_rn(v0);
                    __nv_bfloat16 h1 = __float2bfloat16_rn(v1);
                    __nv_bfloat162 hp; hp.x = h0; hp.y = h1;
                    __nv_bfloat162 lp;
                    lp.x = __float2bfloat16_rn(v0 - __bfloat162float(h0));
                    lp.y = __float2bfloat16_rn(v1 - __bfloat162float(h1));
                    *(__nv_bfloat162*)(dh + (size_t)i * DHn + j2 * 2) = hp;
                    *(__nv_bfloat162*)(dl + (size_t)i * DHn + j2 * 2) = lp;
                }
            }
        } else {
            // V transposed: [bh][d][t]
            __nv_bfloat16* vh = (__nv_bfloat16*)g_Vh4 + (size_t)bh * DHn * Tn;
            __nv_bfloat16* vl = (__nv_bfloat16*)g_Vl4 + (size_t)bh * DHn * Tn;
#pragma unroll
            for (int i = 0; i < 4; i++)
#pragma unroll
                for (int j = 0; j < 4; j++) {
                    float v = acc[i][j];
                    __nv_bfloat16 hi = __float2bfloat16_rn(v);
                    vh[(size_t)(c0 + j) * Tn + t0 + r0 + i] = hi;
                    vl[(size_t)(c0 + j) * Tn + t0 + r0 + i] =
                        __float2bfloat16_rn(v - __bfloat162float(hi));
                }
        }
    }
}

// ---------------------------------------------------------------------------
// Kernel 2: tensor-core flash attention.
// grid = (B*H, T/64), block = 128 (4 warps x m16 queries).
// S = Qhi*Khi + Qhi*Klo + Qlo*Khi   (3-term split, fp32 accum)
// O = Phi*Vhi + Phi*Vlo + Plo*Vhi  (P re-packed from C frags, FA2-style)
// Writes split-bf16 A' rows for the fusion GEMM: [hi | hi | lo].
// ---------------------------------------------------------------------------
__global__ __launch_bounds__(128) void attn_mma_kernel(const int* __restrict__ mask)
{
    const int bh = blockIdx.x;
    const int b = bh >> 4;
    const int h = bh & 15;
    const int q0 = blockIdx.y * 64;
    const int tid = threadIdx.x;
    const int wid = tid >> 5;
    const int lane = tid & 31;
    const int wm = wid * 16;

    __shared__ __nv_bfloat16 Khs[64][72];
    __shared__ __nv_bfloat16 Kls[64][72];
    __shared__ __nv_bfloat16 Vhs[64][72];
    __shared__ __nv_bfloat16 Vls[64][72];
    __shared__ float msk[64];

    // ---- stage Q tile into Khs/Kls, extract A fragments ----
    {
        const __nv_bfloat16* Qh = (const __nv_bfloat16*)g_Qh4 + ((size_t)bh * Tn + q0) * DHn;
        const __nv_bfloat16* Ql = (const __nv_bfloat16*)g_Ql4 + ((size_t)bh * Tn + q0) * DHn;
#pragma unroll
        for (int i = 0; i < 4; i++) {
            int idx = tid + i * 128;
            int row = idx >> 3;
            int c = idx & 7;
            *(uint4*)&Khs[row][c * 8] = *(const uint4*)(Qh + row * DHn + c * 8);
            *(uint4*)&Kls[row][c * 8] = *(const uint4*)(Ql + row * DHn + c * 8);
        }
    }
    __syncthreads();

    uint32_t qh[4][4], ql[4][4];
#pragma unroll
    for (int kt = 0; kt < 4; kt++) {
        uint32_t a0 = smem_u32(&Khs[wm + (lane & 15)][kt * 16 + (lane >> 4) * 8]);
        asm volatile("ldmatrix.sync.aligned.m8n8.x4.shared.b16 {%0,%1,%2,%3}, [%4];"
                     : "=r"(qh[kt][0]), "=r"(qh[kt][1]), "=r"(qh[kt][2]), "=r"(qh[kt][3]) : "r"(a0));
        uint32_t a1 = smem_u32(&Kls[wm + (lane & 15)][kt * 16 + (lane >> 4) * 8]);
        asm volatile("ldmatrix.sync.aligned.m8n8.x4.shared.b16 {%0,%1,%2,%3}, [%4];"
                     : "=r"(ql[kt][0]), "=r"(ql[kt][1]), "=r"(ql[kt][2]), "=r"(ql[kt][3]) : "r"(a1));
    }

    float O[8][4];
#pragma unroll
    for (int nt = 0; nt < 8; nt++)
#pragma unroll
        for (int r = 0; r < 4; r++) O[nt][r] = 0.f;
    float m0 = -1e30f, m1 = -1e30f, l0 = 0.f, l1 = 0.f;

    const __nv_bfloat16* Khg = (const __nv_bfloat16*)g_Kh4 + (size_t)bh * Tn * DHn;
    const __nv_bfloat16* Klg = (const __nv_bfloat16*)g_Kl4 + (size_t)bh * Tn * DHn;
    const __nv_bfloat16* Vhg = (const __nv_bfloat16*)g_Vh4 + (size_t)bh * DHn * Tn;
    const __nv_bfloat16* Vlg = (const __nv_bfloat16*)g_Vl4 + (size_t)bh * DHn * Tn;

    for (int kt0 = 0; kt0 < 8; kt0++) {
        const int t0k = kt0 * 64;
        __syncthreads();
#pragma unroll
        for (int i = 0; i < 4; i++) {
            int idx = tid + i * 128;
            int row = idx >> 3;
            int c = idx & 7;
            *(uint4*)&Khs[row][c * 8] = *(const uint4*)(Khg + (size_t)(t0k + row) * DHn + c * 8);
            *(uint4*)&Kls[row][c * 8] = *(const uint4*)(Klg + (size_t)(t0k + row) * DHn + c * 8);
            *(uint4*)&Vhs[row][c * 8] = *(const uint4*)(Vhg + (size_t)row * Tn + t0k + c * 8);
            *(uint4*)&Vls[row][c * 8] = *(const uint4*)(Vlg + (size_t)row * Tn + t0k + c * 8);
        }
        if (tid < 64) msk[tid] = (mask[b * Tn + t0k + tid] > 0) ? 3.0e38f : -1e9f;
        __syncthreads();

        // ---- S = Q K^T (3-term) ----
        float S[8][4];
#pragma unroll
        for (int nt = 0; nt < 8; nt++)
#pragma unroll
            for (int r = 0; r < 4; r++) S[nt][r] = 0.f;

#pragma unroll
        for (int kt = 0; kt < 4; kt++) {
#pragma unroll
            for (int nt = 0; nt < 8; nt++) {
                uint32_t bh2[2];
                uint32_t addr = smem_u32(&Khs[nt * 8 + (lane & 7)][kt * 16 + ((lane >> 3) & 1) * 8]);
                asm volatile("ldmatrix.sync.aligned.m8n8.x2.shared.b16 {%0,%1}, [%2];"
                             : "=r"(bh2[0]), "=r"(bh2[1]) : "r"(addr));
                mma_bf16(S[nt], qh[kt], bh2);
                mma_bf16(S[nt], ql[kt], bh2);
                uint32_t bl2[2];
                uint32_t addr2 = smem_u32(&Kls[nt * 8 + (lane & 7)][kt * 16 + ((lane >> 3) & 1) * 8]);
                asm volatile("ldmatrix.sync.aligned.m8n8.x2.shared.b16 {%0,%1}, [%2];"
                             : "=r"(bl2[0]), "=r"(bl2[1]) : "r"(addr2));
                mma_bf16(S[nt], qh[kt], bl2);
            }
        }

        // ---- mask + online softmax ----
        float rm0 = -1e30f, rm1 = -1e30f;
#pragma unroll
        for (int nt = 0; nt < 8; nt++) {
            int c = nt * 8 + 2 * (lane & 3);
            float mk0 = msk[c], mk1 = msk[c + 1];
            S[nt][0] = fminf(S[nt][0], mk0);
            S[nt][1] = fminf(S[nt][1], mk1);
            S[nt][2] = fminf(S[nt][2], mk0);
            S[nt][3] = fminf(S[nt][3], mk1);
            rm0 = fmaxf(rm0, fmaxf(S[nt][0], S[nt][1]));
            rm1 = fmaxf(rm1, fmaxf(S[nt][2], S[nt][3]));
        }
        rm0 = fmaxf(rm0, __shfl_xor_sync(0xffffffffu, rm0, 1));
        rm0 = fmaxf(rm0, __shfl_xor_sync(0xffffffffu, rm0, 2));
        rm1 = fmaxf(rm1, __shfl_xor_sync(0xffffffffu, rm1, 1));
        rm1 = fmaxf(rm1, __shfl_xor_sync(0xffffffffu, rm1, 2));

        float m0n = fmaxf(m0, rm0), m1n = fmaxf(m1, rm1);
        float c0f = __expf(m0 - m0n), c1f = __expf(m1 - m1n);
        l0 *= c0f; l1 *= c1f;
#pragma unroll
        for (int nt = 0; nt < 8; nt++) {
            O[nt][0] *= c0f; O[nt][1] *= c0f;
            O[nt][2] *= c1f; O[nt][3] *= c1f;
        }
        m0 = m0n; m1 = m1n;

        float ps0 = 0.f, ps1 = 0.f;
#pragma unroll
        for (int nt = 0; nt < 8; nt++) {
            S[nt][0] = __expf(S[nt][0] - m0);
            S[nt][1] = __expf(S[nt][1] - m0);
            S[nt][2] = __expf(S[nt][2] - m1);
            S[nt][3] = __expf(S[nt][3] - m1);
            ps0 += S[nt][0] + S[nt][1];
            ps1 += S[nt][2] + S[nt][3];
        }
        l0 += ps0; l1 += ps1;

        // ---- O += P V (3-term; P frags built from S regs) ----
#pragma unroll
        for (int kt = 0; kt < 4; kt++) {
            float p00 = S[2 * kt][0], p01 = S[2 * kt][1], p02 = S[2 * kt][2], p03 = S[2 * kt][3];
            float p10 = S[2 * kt + 1][0], p11 = S[2 * kt + 1][1], p12 = S[2 * kt + 1][2], p13 = S[2 * kt + 1][3];
            __nv_bfloat16 h00 = __float2bfloat16_rn(p00), h01 = __float2bfloat16_rn(p01);
            __nv_bfloat16 h02 = __float2bfloat16_rn(p02), h03 = __float2bfloat16_rn(p03);
            __nv_bfloat16 h10 = __float2bfloat16_rn(p10), h11 = __float2bfloat16_rn(p11);
            __nv_bfloat16 h12 = __float2bfloat16_rn(p12), h13 = __float2bfloat16_rn(p13);
            uint32_t ah[4], al[4];
            { __nv_bfloat162 t; t.x = h00; t.y = h01; ah[0] = *(uint32_t*)&t; }
            { __nv_bfloat162 t; t.x = h02; t.y = h03; ah[1] = *(uint32_t*)&t; }
            { __nv_bfloat162 t; t.x = h10; t.y = h11; ah[2] = *(uint32_t*)&t; }
            { __nv_bfloat162 t; t.x = h12; t.y = h13; ah[3] = *(uint32_t*)&t; }
            al[0] = pack_bf16(p00 - __bfloat162float(h00), p01 - __bfloat162float(h01));
            al[1] = pack_bf16(p02 - __bfloat162float(h02), p03 - __bfloat162float(h03));
            al[2] = pack_bf16(p10 - __bfloat162float(h10), p11 - __bfloat162float(h11));
            al[3] = pack_bf16(p12 - __bfloat162float(h12), p13 - __bfloat162float(h13));
#pragma unroll
            for (int nt = 0; nt < 8; nt++) {
                uint32_t bvh[2];
                uint32_t addr = smem_u32(&Vhs[nt * 8 + (lane & 7)][kt * 16 + ((lane >> 3) & 1) * 8]);
                asm volatile("ldmatrix.sync.aligned.m8n8.x2.shared.b16 {%0,%1}, [%2];"
                             : "=r"(bvh[0]), "=r"(bvh[1]) : "r"(addr));
                mma_bf16(O[nt], ah, bvh);
                mma_bf16(O[nt], al, bvh);
                uint32_t bvl[2];
                uint32_t addr2 = smem_u32(&Vls[nt * 8 + (lane & 7)][kt * 16 + ((lane >> 3) & 1) * 8]);
                asm volatile("ldmatrix.sync.aligned.m8n8.x2.shared.b16 {%0,%1}, [%2];"
                             : "=r"(bvl[0]), "=r"(bvl[1]) : "r"(addr2));
                mma_bf16(O[nt], ah, bvl);
            }
        }
    }

    // ---- epilogue ----
    l0 += __shfl_xor_sync(0xffffffffu, l0, 1);
    l0 += __shfl_xor_sync(0xffffffffu, l0, 2);
    l1 += __shfl_xor_sync(0xffffffffu, l1, 1);
    l1 += __shfl_xor_sync(0xffffffffu, l1, 2);
    const float inv0 = 1.f / l0;
    const float inv1 = 1.f / l1;

    const int row0 = b * Tn + q0 + wm + (lane >> 2);
    const int row1 = row0 + 8;
    __nv_bfloat16* Ap = (__nv_bfloat16*)g_A4;
#pragma unroll
    for (int nt = 0; nt < 8; nt++) {
        const int col = h * DHn + nt * 8 + 2 * (lane & 3);
        float o00 = O[nt][0] * inv0, o01 = O[nt][1] * inv0;
        float o10 = O[nt][2] * inv1, o11 = O[nt][3] * inv1;
        __nv_bfloat16 h00 = __float2bfloat16_rn(o00), h01 = __float2bfloat16_rn(o01);
        __nv_bfloat16 h10 = __float2bfloat16_rn(o10), h11 = __float2bfloat16_rn(o11);
        uint32_t hp0, hp1;
        { __nv_bfloat162 t; t.x = h00; t.y = h01; hp0 = *(uint32_t*)&t; }
        { __nv_bfloat162 t; t.x = h10; t.y = h11; hp1 = *(uint32_t*)&t; }
        uint32_t lp0 = pack_bf16(o00 - __bfloat162float(h00), o01 - __bfloat162float(h01));
        uint32_t lp1 = pack_bf16(o10 - __bfloat162float(h10), o11 - __bfloat162float(h11));
        *(uint32_t*)(Ap + (size_t)row0 * FK + col)        = hp0;
        *(uint32_t*)(Ap + (size_t)row0 * FK + 1024 + col) = hp0;
        *(uint32_t*)(Ap + (size_t)row0 * FK + 2048 + col) = lp0;
        *(uint32_t*)(Ap + (size_t)row1 * FK + col)        = hp1;
        *(uint32_t*)(Ap + (size_t)row1 * FK + 1024 + col) = hp1;
        *(uint32_t*)(Ap + (size_t)row1 * FK + 2048 + col) = lp1;
    }
}

// ---------------------------------------------------------------------------
// Kernel 3: build B' = split-bf16 transpose of Wf.
// ---------------------------------------------------------------------------
__global__ __launch_bounds__(256) void convw_kernel(const float* __restrict__ Wf)
{
    __shared__ float t[32][33];
    const int tx = threadIdx.x & 31, ty = threadIdx.x >> 5;
    const int n0 = blockIdx.x * 32, k0 = blockIdx.y * 32;

#pragma unroll
    for (int r = 0; r < 4; r++)
        t[ty + r * 8][tx] = Wf[(size_t)(k0 + ty + r * 8) * Dn + n0 + tx];
    __syncthreads();

    __nv_bfloat16* Bg = (__nv_bfloat16*)g_B4;
#pragma unroll
    for (int r = 0; r < 4; r++) {
        int n = n0 + ty + r * 8;
        int k = k0 + tx;
        float w = t[tx][ty + r * 8];
        __nv_bfloat16 hi = __float2bfloat16_rn(w);
        __nv_bfloat16 lo = __float2bfloat16_rn(w - __bfloat162float(hi));
        size_t base = (size_t)n * FK + k;
        Bg[base]        = hi;
        Bg[base + 1024] = lo;
        Bg[base + 2048] = hi;
    }
}

// ---------------------------------------------------------------------------
// Kernel 4: fusion GEMM via mma.sync (unchanged from round 6; 111us measured).
// ---------------------------------------------------------------------------
#define FNCH (FK / 32)   // 96 chunks

__global__ __launch_bounds__(256) void fuse_mma_kernel(
    const float* __restrict__ bfv, float* __restrict__ out)
{
    __shared__ __nv_bfloat16 As[2][128][40];
    __shared__ __nv_bfloat16 Bs[2][128][40];

    const int tid = threadIdx.x;
    const int wid = tid >> 5;
    const int lane = tid & 31;
    const int bm = blockIdx.y * 128;
    const int bn = blockIdx.x * 128;
    const int wm = (wid >> 1) * 32;
    const int wn = (wid & 1) * 64;

    const __nv_bfloat16* Ag = (const __nv_bfloat16*)g_A4;
    const __nv_bfloat16* Bg = (const __nv_bfloat16*)g_B4;

    float acc[2][8][4];
#pragma unroll
    for (int mt = 0; mt < 2; mt++)
#pragma unroll
        for (int nt = 0; nt < 8; nt++)
#pragma unroll
            for (int r = 0; r < 4; r++) acc[mt][nt][r] = 0.f;

    const int l_row = tid >> 2;
    const int l_c16 = tid & 3;

    {
#pragma unroll
        for (int i = 0; i < 2; i++) {
            int row = l_row + i * 64;
            *(uint4*)&As[0][row][l_c16 * 8] = *(const uint4*)(Ag + (size_t)(bm + row) * FK + l_c16 * 8);
            *(uint4*)&Bs[0][row][l_c16 * 8] = *(const uint4*)(Bg + (size_t)(bn + row) * FK + l_c16 * 8);
        }
    }
    __syncthreads();

    for (int c = 0; c < FNCH; c++) {
        const int buf = c & 1;
        uint4 pa[2], pb[2];
        if (c + 1 < FNCH) {
#pragma unroll
            for (int i = 0; i < 2; i++) {
                int row = l_row + i * 64;
                pa[i] = *(const uint4*)(Ag + (size_t)(bm + row) * FK + (c + 1) * 32 + l_c16 * 8);
                pb[i] = *(const uint4*)(Bg + (size_t)(bn + row) * FK + (c + 1) * 32 + l_c16 * 8);
            }
        }

#pragma unroll
        for (int ks = 0; ks < 2; ks++) {
            const int k0 = ks * 16;
            uint32_t af[2][4];
#pragma unroll
            for (int mt = 0; mt < 2; mt++) {
                uint32_t addr = smem_u32(&As[buf][wm + mt * 16 + (lane & 15)][k0 + (lane >> 4) * 8]);
                asm volatile("ldmatrix.sync.aligned.m8n8.x4.shared.b16 {%0,%1,%2,%3}, [%4];"
                             : "=r"(af[mt][0]), "=r"(af[mt][1]), "=r"(af[mt][2]), "=r"(af[mt][3])
                             : "r"(addr));
            }
            uint32_t bfr[8][2];
#pragma unroll
            for (int nt = 0; nt < 8; nt++) {
                uint32_t addr = smem_u32(&Bs[buf][wn + nt * 8 + (lane & 7)][k0 + ((lane >> 3) & 1) * 8]);
                asm volatile("ldmatrix.sync.aligned.m8n8.x2.shared.b16 {%0,%1}, [%2];"
                             : "=r"(bfr[nt][0]), "=r"(bfr[nt][1]) : "r"(addr));
            }
#pragma unroll
            for (int mt = 0; mt < 2; mt++)
#pragma unroll
                for (int nt = 0; nt < 8; nt++)
                    mma_bf16(acc[mt][nt], af[mt], bfr[nt]);
        }

        if (c + 1 < FNCH) {
            const int nb = buf ^ 1;
#pragma unroll
            for (int i = 0; i < 2; i++) {
                int row = l_row + i * 64;
                *(uint4*)&As[nb][row][l_c16 * 8] = pa[i];
                *(uint4*)&Bs[nb][row][l_c16 * 8] = pb[i];
            }
        }
        __syncthreads();
    }

#pragma unroll
    for (int mt = 0; mt < 2; mt++) {
        const int row0 = bm + wm + mt * 16 + (lane >> 2);
#pragma unroll
        for (int nt = 0; nt < 8; nt++) {
            const int col = bn + wn + nt * 8 + (lane & 3) * 2;
            const float b0 = bfv[col], b1 = bfv[col + 1];
            float* p0 = out + (size_t)row0 * Dn + col;
            float* p1 = out + (size_t)(row0 + 8) * Dn + col;
            p0[0] = acc[mt][nt][0] + b0;
            p0[1] = acc[mt][nt][1] + b1;
            p1[0] = acc[mt][nt][2] + b0;
            p1[1] = acc[mt][nt][3] + b1;
        }
    }
}

// ---------------------------------------------------------------------------
extern "C" void kernel_launch(void* const* d_in, const int* in_sizes, int n_in,
                              void* d_out, int out_size)
{
    const float* X    = (const float*)d_in[0];
    const int*   mask = (const int*)  d_in[1];
    const float* Wq   = (const float*)d_in[2];
    const float* bq   = (const float*)d_in[3];
    const float* Wk   = (const float*)d_in[4];
    const float* bk   = (const float*)d_in[5];
    const float* Wv   = (const float*)d_in[6];
    const float* bv   = (const float*)d_in[7];
    const float* Wf   = (const float*)d_in[8];
    const float* bfp  = (const float*)d_in[9];
    float* out = (float*)d_out;

    qkv_kernel<<<dim3(Bn * Hn, Tn / 64), 256>>>(X, Wq, bq, Wk, bk, Wv, bv);
    attn_mma_kernel<<<dim3(Bn * Hn, Tn / 64), 128>>>(mask);
    convw_kernel<<<dim3(Dn / 32, Dn / 32), 256>>>(Wf);
    fuse_mma_kernel<<<dim3(Dn / 128, (Bn * Tn) / 128), 256>>>(bfp, out);
}